// round 1
// baseline (speedup 1.0000x reference)
#include <cuda_runtime.h>
#include <math.h>

#define BB 2
#define SS 512
#define DD 768
#define HH 12
#define NLAYER 6
#define VV 32000
#define HDIM 64
#define DFF 3072
#define EPSF 1e-6f

// ---------------- scratch (device globals; no allocs allowed) ----------------
__device__ float g_h  [BB*SS*DD];
__device__ float g_hn [BB*SS*DD];
__device__ float g_q  [BB*SS*DD];
__device__ float g_k  [BB*SS*DD];
__device__ float g_v  [BB*SS*DD];
__device__ float g_ctx[BB*SS*DD];
__device__ float g_ffn[BB*SS*DFF];
__device__ float g_sc [BB*HH*SS*SS];

// ---------------- embedding ----------------
__global__ void embed_kernel(const int* __restrict__ x, const float* __restrict__ tok,
                             const float* __restrict__ pos, float* __restrict__ out) {
    int idx = blockIdx.x * blockDim.x + threadIdx.x;
    if (idx >= BB*SS*DD) return;
    int d  = idx % DD;
    int bs = idx / DD;
    int s  = bs % SS;
    out[idx] = tok[(long long)x[bs]*DD + d] + pos[s*DD + d];
}

// ---------------- "DummyNorm": s*(x-mean)/(std_ddof1 + eps) + b ----------------
__global__ void norm_kernel(const float* __restrict__ x, const float* __restrict__ sc,
                            const float* __restrict__ bi, float* __restrict__ y) {
    int row = blockIdx.x;                 // B*S rows
    const float* xr = x + (long long)row * DD;
    float* yr = y + (long long)row * DD;
    int tid = threadIdx.x;
    float sum = 0.f, sq = 0.f;
    for (int i = tid; i < DD; i += 256) { float v = xr[i]; sum += v; sq += v*v; }
    __shared__ float s1[256], s2[256];
    s1[tid] = sum; s2[tid] = sq; __syncthreads();
    for (int st = 128; st > 0; st >>= 1) {
        if (tid < st) { s1[tid] += s1[tid+st]; s2[tid] += s2[tid+st]; }
        __syncthreads();
    }
    float mean = s1[0] / (float)DD;
    float var  = (s2[0] - (float)DD * mean * mean) / (float)(DD - 1);
    float inv  = 1.f / (sqrtf(fmaxf(var, 0.f)) + EPSF);
    for (int i = tid; i < DD; i += 256) yr[i] = sc[i] * (xr[i] - mean) * inv + bi[i];
}

// ---------------- masked+scaled softmax over key axis ----------------
// mask: strictly-lower-tri (k < q) -> -inf  => valid keys are k >= q
__global__ void softmax_kernel(float* __restrict__ scores) {
    int row = blockIdx.x;                 // b*H*S + h*S + q
    int q = row % SS;
    float* p = scores + (long long)row * SS;
    int tid = threadIdx.x;
    const float scale = 0.125f;           // 1/sqrt(64)
    float m = -1e30f;
    for (int k = q + tid; k < SS; k += 128) m = fmaxf(m, p[k] * scale);
    __shared__ float sh[128];
    sh[tid] = m; __syncthreads();
    for (int st = 64; st > 0; st >>= 1) { if (tid < st) sh[tid] = fmaxf(sh[tid], sh[tid+st]); __syncthreads(); }
    m = sh[0]; __syncthreads();
    float sum = 0.f;
    for (int k = q + tid; k < SS; k += 128) { float e = __expf(p[k]*scale - m); p[k] = e; sum += e; }
    sh[tid] = sum; __syncthreads();
    for (int st = 64; st > 0; st >>= 1) { if (tid < st) sh[tid] += sh[tid+st]; __syncthreads(); }
    float inv = 1.f / sh[0];
    for (int k = q + tid; k < SS; k += 128) p[k] *= inv;
    for (int k = tid; k < q; k += 128) p[k] = 0.f;
}

// ---------------- generic tiled SGEMM with fused epilogue ----------------
// C[m,n] = sum_k A[m,k] * (TRANSB ? B[n,k] : B[k,n]); optional +bias[n], GELU, +res[m,n]
// batch via blockIdx.z: zd = z / zdiv, zm = z % zdiv; base offsets zd*sX1 + zm*sX2
template<int TRANSB>
__global__ void __launch_bounds__(256)
gemm_kernel(const float* __restrict__ A, const float* __restrict__ Bm,
            const float* __restrict__ bias, const float* __restrict__ res,
            float* __restrict__ C,
            int K, int lda, int ldb, int ldc, int act, int zdiv,
            long long sa1, long long sa2, long long sb1, long long sb2,
            long long sc1, long long sc2)
{
    __shared__ float As[64][16];
    __shared__ float Bs[TRANSB ? 64*17 : 16*72];

    int z  = blockIdx.z;
    int zd = z / zdiv, zm = z % zdiv;
    const float* Ab = A  + zd*sa1 + zm*sa2;
    const float* Bb = Bm + zd*sb1 + zm*sb2;
    float*       Cb = C  + zd*sc1 + zm*sc2;
    const float* Rb = res ? (res + zd*sc1 + zm*sc2) : (const float*)0;

    int tid = threadIdx.x;                   // 256
    int tx = tid & 15, ty = tid >> 4;
    int m0 = blockIdx.y * 64;
    int n0 = blockIdx.x * 64;

    int arow = tid >> 2;                     // 0..63
    int acol = (tid & 3) * 4;                // 0,4,8,12

    float acc[4][4] = {};
    for (int kt = 0; kt < K; kt += 16) {
        // A tile: As[m_local][k_local], float4 coalesced loads
        float4 a4 = *(const float4*)(Ab + (long long)(m0 + arow)*lda + kt + acol);
        *(float4*)&As[arow][acol] = a4;
        if (TRANSB) {
            // B[n,k] -> Bs[n][k] ([64][17])
            float4 b4 = *(const float4*)(Bb + (long long)(n0 + arow)*ldb + kt + acol);
            Bs[arow*17 + acol + 0] = b4.x;
            Bs[arow*17 + acol + 1] = b4.y;
            Bs[arow*17 + acol + 2] = b4.z;
            Bs[arow*17 + acol + 3] = b4.w;
        } else {
            // B[k,n] -> Bs[k][n] ([16][72])
            int brow = tid >> 4;             // k 0..15
            int bcol = (tid & 15) * 4;       // n
            float4 b4 = *(const float4*)(Bb + (long long)(kt + brow)*ldb + n0 + bcol);
            *(float4*)&Bs[brow*72 + bcol] = b4;
        }
        __syncthreads();
        #pragma unroll
        for (int k = 0; k < 16; k++) {
            float a0 = As[ty*4+0][k], a1 = As[ty*4+1][k], a2 = As[ty*4+2][k], a3 = As[ty*4+3][k];
            float b0, b1, b2, b3;
            if (TRANSB) {
                b0 = Bs[(tx*4+0)*17 + k]; b1 = Bs[(tx*4+1)*17 + k];
                b2 = Bs[(tx*4+2)*17 + k]; b3 = Bs[(tx*4+3)*17 + k];
            } else {
                float4 bv = *(const float4*)&Bs[k*72 + tx*4];
                b0 = bv.x; b1 = bv.y; b2 = bv.z; b3 = bv.w;
            }
            acc[0][0] += a0*b0; acc[0][1] += a0*b1; acc[0][2] += a0*b2; acc[0][3] += a0*b3;
            acc[1][0] += a1*b0; acc[1][1] += a1*b1; acc[1][2] += a1*b2; acc[1][3] += a1*b3;
            acc[2][0] += a2*b0; acc[2][1] += a2*b1; acc[2][2] += a2*b2; acc[2][3] += a2*b3;
            acc[3][0] += a3*b0; acc[3][1] += a3*b1; acc[3][2] += a3*b2; acc[3][3] += a3*b3;
        }
        __syncthreads();
    }
    #pragma unroll
    for (int i = 0; i < 4; i++) {
        int m = m0 + ty*4 + i;
        #pragma unroll
        for (int j = 0; j < 4; j++) {
            int n = n0 + tx*4 + j;
            float v = acc[i][j];
            if (bias) v += bias[n];
            if (act == 1) {
                float t = v + 0.044715f * v * v * v;
                v = 0.5f * v * (1.0f + tanhf(0.7978845608028654f * t));
            }
            if (Rb) v += Rb[(long long)m*ldc + n];
            Cb[(long long)m*ldc + n] = v;
        }
    }
}

static void launch_gemm(const float* A, const float* Bm, const float* bias, const float* res,
                        float* C, int M, int N, int K, int lda, int ldb, int ldc,
                        int act, int batch, int transB, int zdiv,
                        long long sa1, long long sa2, long long sb1, long long sb2,
                        long long sc1, long long sc2)
{
    dim3 grid(N/64, M/64, batch), blk(256);
    if (transB)
        gemm_kernel<1><<<grid, blk>>>(A, Bm, bias, res, C, K, lda, ldb, ldc, act, zdiv,
                                      sa1, sa2, sb1, sb2, sc1, sc2);
    else
        gemm_kernel<0><<<grid, blk>>>(A, Bm, bias, res, C, K, lda, ldb, ldc, act, zdiv,
                                      sa1, sa2, sb1, sb2, sc1, sc2);
}

extern "C" void kernel_launch(void* const* d_in, const int* in_sizes, int n_in,
                              void* d_out, int out_size)
{
    const int*   x   = (const int*)  d_in[0];
    const float* tok = (const float*)d_in[1];
    const float* pos = (const float*)d_in[2];
    const float* n1s = (const float*)d_in[3];
    const float* n1b = (const float*)d_in[4];
    const float* n2s = (const float*)d_in[5];
    const float* n2b = (const float*)d_in[6];
    const float* wq  = (const float*)d_in[7];
    const float* wk  = (const float*)d_in[8];
    const float* wv  = (const float*)d_in[9];
    const float* wo  = (const float*)d_in[10];
    const float* bo  = (const float*)d_in[11];
    const float* w1  = (const float*)d_in[12];
    const float* b1  = (const float*)d_in[13];
    const float* w2  = (const float*)d_in[14];
    const float* b2  = (const float*)d_in[15];
    const float* fs  = (const float*)d_in[16];
    const float* fb  = (const float*)d_in[17];
    const float* hw  = (const float*)d_in[18];
    const float* hb  = (const float*)d_in[19];
    float* out = (float*)d_out;

    float *h, *hn, *gq, *gk, *gv, *ctx, *ffn, *sc;
    cudaGetSymbolAddress((void**)&h,   g_h);
    cudaGetSymbolAddress((void**)&hn,  g_hn);
    cudaGetSymbolAddress((void**)&gq,  g_q);
    cudaGetSymbolAddress((void**)&gk,  g_k);
    cudaGetSymbolAddress((void**)&gv,  g_v);
    cudaGetSymbolAddress((void**)&ctx, g_ctx);
    cudaGetSymbolAddress((void**)&ffn, g_ffn);
    cudaGetSymbolAddress((void**)&sc,  g_sc);

    const int M = BB * SS;                         // 1024
    const long long SD  = (long long)SS * DD;      // per-batch stride in q/k/v/h
    const long long SSs = (long long)SS * SS;      // per-head stride in scores

    embed_kernel<<<(BB*SS*DD + 255)/256, 256>>>(x, tok, pos, h);

    for (int l = 0; l < NLAYER; l++) {
        norm_kernel<<<M, 256>>>(h, n1s + l*DD, n1b + l*DD, hn);

        launch_gemm(hn, wq + (long long)l*DD*DD, 0, 0, gq, M, DD, DD, DD, DD, DD, 0, 1, 0, 1, 0,0,0,0,0,0);
        launch_gemm(hn, wk + (long long)l*DD*DD, 0, 0, gk, M, DD, DD, DD, DD, DD, 0, 1, 0, 1, 0,0,0,0,0,0);
        launch_gemm(hn, wv + (long long)l*DD*DD, 0, 0, gv, M, DD, DD, DD, DD, DD, 0, 1, 0, 1, 0,0,0,0,0,0);

        // scores[b,h,q,k] = Q . K  (batched over b*H, transB)
        launch_gemm(gq, gk, 0, 0, sc, SS, SS, HDIM, DD, DD, SS, 0, BB*HH, 1, HH,
                    SD, HDIM, SD, HDIM, (long long)HH*SSs, SSs);

        softmax_kernel<<<BB*HH*SS, 128>>>(sc);

        // ctx[b,q,h,:] = P @ V  (batched over b*H)
        launch_gemm(sc, gv, 0, 0, ctx, SS, HDIM, SS, SS, DD, DD, 0, BB*HH, 0, HH,
                    (long long)HH*SSs, SSs, SD, HDIM, SD, HDIM);

        // x = res + ctx @ wo + bo
        launch_gemm(ctx, wo + (long long)l*DD*DD, bo + l*DD, h, h, M, DD, DD, DD, DD, DD, 0, 1, 0, 1, 0,0,0,0,0,0);

        norm_kernel<<<M, 256>>>(h, n2s + l*DD, n2b + l*DD, hn);

        // ffn = gelu(hn @ w1 + b1)
        launch_gemm(hn, w1 + (long long)l*DD*DFF, b1 + l*DFF, 0, ffn, M, DFF, DD, DD, DFF, DFF, 1, 1, 0, 1, 0,0,0,0,0,0);
        // x = res + ffn @ w2 + b2
        launch_gemm(ffn, w2 + (long long)l*DFF*DD, b2 + l*DD, h, h, M, DD, DFF, DFF, DD, DD, 0, 1, 0, 1, 0,0,0,0,0,0);
    }

    norm_kernel<<<M, 256>>>(h, fs, fb, hn);
    // logits = hn @ head_w + head_b
    launch_gemm(hn, hw, hb, 0, out, M, VV, DD, DD, VV, VV, 0, 1, 0, 1, 0,0,0,0,0,0);
}